// round 1
// baseline (speedup 1.0000x reference)
#include <cuda_runtime.h>
#include <math.h>

#define NB 48
#define SS 1024
#define DD 128
#define DKK 64

// scratch (static device globals: allocation-free per harness rules)
__device__ float g_Q[NB * SS * DKK];
__device__ float g_K[NB * SS * DKK];
__device__ float g_Z[NB];

// ---------------------------------------------------------------------------
// Kernel 1: fused Q|K projection.
// A: [48*1024, 128] row-major. Wq, Wk: [128, 64] row-major.
// Output tile per CTA: 128 rows x 128 cols (cols 0..63 -> g_Q, 64..127 -> g_K).
// Classic SGEMM tiling: Ktile = 16, 256 threads, 8x8 micro-tile per thread.
// Also zeroes g_Z (runs before score kernel in-stream).
// ---------------------------------------------------------------------------
__global__ __launch_bounds__(256) void proj_kernel(
    const float* __restrict__ A,
    const float* __restrict__ Wq,
    const float* __restrict__ Wk)
{
    if (blockIdx.x == 0 && threadIdx.x < NB) g_Z[threadIdx.x] = 0.f;

    __shared__ float sA[128][17];   // [m][k] padded
    __shared__ float sB[16][128];   // [k][c]

    const int tid = threadIdx.x;
    const int tx = tid & 15, ty = tid >> 4;
    const int rowbase = blockIdx.x * 128;

    float acc[8][8];
#pragma unroll
    for (int i = 0; i < 8; i++)
#pragma unroll
        for (int j = 0; j < 8; j++) acc[i][j] = 0.f;

    for (int k0 = 0; k0 < DD; k0 += 16) {
        // load A tile: 128 rows x 16 k  (512 float4 / 256 threads = 2 each)
#pragma unroll
        for (int it = 0; it < 2; it++) {
            int f = tid + 256 * it;
            int m = f >> 2, kq = (f & 3) * 4;
            float4 v = *(const float4*)(A + (size_t)(rowbase + m) * DD + k0 + kq);
            sA[m][kq + 0] = v.x; sA[m][kq + 1] = v.y;
            sA[m][kq + 2] = v.z; sA[m][kq + 3] = v.w;
        }
        // load W tile: 16 k x 128 c (Wq | Wk)
#pragma unroll
        for (int it = 0; it < 2; it++) {
            int f = tid + 256 * it;
            int k = f >> 5, c4 = (f & 31) * 4;
            float4 v = (c4 < 64)
                ? *(const float4*)(Wq + (k0 + k) * DKK + c4)
                : *(const float4*)(Wk + (k0 + k) * DKK + (c4 - 64));
            *(float4*)&sB[k][c4] = v;
        }
        __syncthreads();
#pragma unroll
        for (int k = 0; k < 16; k++) {
            float ra[8], rb[8];
#pragma unroll
            for (int i = 0; i < 8; i++) ra[i] = sA[ty + 16 * i][k];
#pragma unroll
            for (int j = 0; j < 8; j++) rb[j] = sB[k][tx + 16 * j];
#pragma unroll
            for (int i = 0; i < 8; i++)
#pragma unroll
                for (int j = 0; j < 8; j++)
                    acc[i][j] = fmaf(ra[i], rb[j], acc[i][j]);
        }
        __syncthreads();
    }

#pragma unroll
    for (int i = 0; i < 8; i++) {
        int m = rowbase + ty + 16 * i;
#pragma unroll
        for (int j = 0; j < 8; j++) {
            int c = tx + 16 * j;          // compile-time resolvable branch per j
            if (c < 64) g_Q[(size_t)m * DKK + c] = acc[i][j];
            else        g_K[(size_t)m * DKK + (c - 64)] = acc[i][j];
        }
    }
}

// ---------------------------------------------------------------------------
// Kernel 2: per-batch score tile 128x128 = Qtile @ Ktile^T  (K-dim = 64).
// Fused epilogue:  u = exp(10*tanh(x)) * e^{-10} = exp(-20 / (e^{2x}+1))
// (the e^{-10} factor cancels in the softmax normalization).
// Diagonal (q==s) forced to 0 (== exp(-1e8) after softmax).
// Writes unnormalized u to out; block-reduces partial sum into g_Z[b].
// ---------------------------------------------------------------------------
__global__ __launch_bounds__(256) void score_kernel(float* __restrict__ out)
{
    __shared__ float sQ[128][36];   // [row][k-chunk 32] padded to 36 (float4-aligned)
    __shared__ float sK[128][36];

    const int tid = threadIdx.x;
    const int tx = tid & 15, ty = tid >> 4;
    const int bz = blockIdx.z;
    const int qbase = blockIdx.y * 128;
    const int sbase = blockIdx.x * 128;

    const float* Qb = g_Q + (size_t)bz * SS * DKK;
    const float* Kb = g_K + (size_t)bz * SS * DKK;

    float acc[8][8];
#pragma unroll
    for (int i = 0; i < 8; i++)
#pragma unroll
        for (int j = 0; j < 8; j++) acc[i][j] = 0.f;

    for (int k0 = 0; k0 < DKK; k0 += 32) {
        // 128 rows x 32 k each for Q and K: 1024 float4 / 256 threads = 4 each
#pragma unroll
        for (int it = 0; it < 4; it++) {
            int f = tid + 256 * it;
            int m = f >> 3, k4 = (f & 7) * 4;
            *(float4*)&sQ[m][k4] =
                *(const float4*)(Qb + (size_t)(qbase + m) * DKK + k0 + k4);
            *(float4*)&sK[m][k4] =
                *(const float4*)(Kb + (size_t)(sbase + m) * DKK + k0 + k4);
        }
        __syncthreads();
#pragma unroll
        for (int k = 0; k < 32; k++) {
            float ra[8], rb[8];
#pragma unroll
            for (int i = 0; i < 8; i++) ra[i] = sQ[ty + 16 * i][k];
#pragma unroll
            for (int j = 0; j < 8; j++) rb[j] = sK[tx + 16 * j][k];
#pragma unroll
            for (int i = 0; i < 8; i++)
#pragma unroll
                for (int j = 0; j < 8; j++)
                    acc[i][j] = fmaf(ra[i], rb[j], acc[i][j]);
        }
        __syncthreads();
    }

    float local = 0.f;
    float* orow = out + ((size_t)bz << 20);
#pragma unroll
    for (int i = 0; i < 8; i++) {
        int qg = qbase + ty + 16 * i;
#pragma unroll
        for (int j = 0; j < 8; j++) {
            int sg = sbase + tx + 16 * j;
            float x  = acc[i][j];
            float e2 = __expf(2.f * x);                       // e^{2x} (inf ok)
            float u  = __expf(-__fdividef(20.f, e2 + 1.f));   // 20/inf -> 0 -> u=1
            if (qg == sg) u = 0.f;                            // diagonal mask
            orow[(size_t)qg * SS + sg] = u;
            local += u;
        }
    }
    // warp reduce + one atomic per warp
#pragma unroll
    for (int o = 16; o; o >>= 1)
        local += __shfl_down_sync(0xffffffffu, local, o);
    if ((tid & 31) == 0) atomicAdd(&g_Z[bz], local);
}

// ---------------------------------------------------------------------------
// Kernel 3: normalize by 1/Z[b]. float4 vectorized, one element per thread.
// grid (1024, 48) x 256 threads x float4 = S*S per batch.
// ---------------------------------------------------------------------------
__global__ __launch_bounds__(256) void norm_kernel(float4* __restrict__ out)
{
    __shared__ float sinv;
    const int b = blockIdx.y;
    if (threadIdx.x == 0) sinv = 1.0f / g_Z[b];
    __syncthreads();
    const float inv = sinv;

    size_t idx = ((size_t)b << 18) + (size_t)blockIdx.x * 256 + threadIdx.x;
    float4 v = out[idx];
    v.x *= inv; v.y *= inv; v.z *= inv; v.w *= inv;
    out[idx] = v;
}

// ---------------------------------------------------------------------------
extern "C" void kernel_launch(void* const* d_in, const int* in_sizes, int n_in,
                              void* d_out, int out_size)
{
    const float* q  = (const float*)d_in[0];   // query [48,1024,128]
    // d_in[1] = exchange, d_in[2] = solution_indexes : unused by reference
    const float* wq = (const float*)d_in[3];   // W_query [128,64]
    const float* wk = (const float*)d_in[4];   // W_key   [128,64]
    float* out = (float*)d_out;                // [48, 1024*1024] fp32

    proj_kernel<<<384, 256>>>(q, wq, wk);
    score_kernel<<<dim3(8, 8, NB), 256>>>(out);
    norm_kernel<<<dim3(1024, NB), 256>>>((float4*)out);
}

// round 2
// speedup vs baseline: 1.4593x; 1.4593x over previous
#include <cuda_runtime.h>
#include <math.h>
#include <stdint.h>

#define NB 48
#define SS 1024
#define DD 128
#define DKK 64

// scratch (static device globals: allocation-free per harness rules)
__device__ float g_Q[NB * SS * DKK];
__device__ float g_K[NB * SS * DKK];
__device__ float g_Z[NB];

__device__ __forceinline__ uint32_t f2tf32(float v) {
    uint32_t r;
    asm("cvt.rna.tf32.f32 %0, %1;" : "=r"(r) : "f"(v));
    return r;
}

// ---------------------------------------------------------------------------
// Kernel 1: fused Q|K projection (fp32 exact, unchanged from R1).
// ---------------------------------------------------------------------------
__global__ __launch_bounds__(256) void proj_kernel(
    const float* __restrict__ A,
    const float* __restrict__ Wq,
    const float* __restrict__ Wk)
{
    if (blockIdx.x == 0 && threadIdx.x < NB) g_Z[threadIdx.x] = 0.f;

    __shared__ float sA[128][17];
    __shared__ float sB[16][128];

    const int tid = threadIdx.x;
    const int tx = tid & 15, ty = tid >> 4;
    const int rowbase = blockIdx.x * 128;

    float acc[8][8];
#pragma unroll
    for (int i = 0; i < 8; i++)
#pragma unroll
        for (int j = 0; j < 8; j++) acc[i][j] = 0.f;

    for (int k0 = 0; k0 < DD; k0 += 16) {
#pragma unroll
        for (int it = 0; it < 2; it++) {
            int f = tid + 256 * it;
            int m = f >> 2, kq = (f & 3) * 4;
            float4 v = *(const float4*)(A + (size_t)(rowbase + m) * DD + k0 + kq);
            sA[m][kq + 0] = v.x; sA[m][kq + 1] = v.y;
            sA[m][kq + 2] = v.z; sA[m][kq + 3] = v.w;
        }
#pragma unroll
        for (int it = 0; it < 2; it++) {
            int f = tid + 256 * it;
            int k = f >> 5, c4 = (f & 31) * 4;
            float4 v = (c4 < 64)
                ? *(const float4*)(Wq + (k0 + k) * DKK + c4)
                : *(const float4*)(Wk + (k0 + k) * DKK + (c4 - 64));
            *(float4*)&sB[k][c4] = v;
        }
        __syncthreads();
#pragma unroll
        for (int k = 0; k < 16; k++) {
            float ra[8], rb[8];
#pragma unroll
            for (int i = 0; i < 8; i++) ra[i] = sA[ty + 16 * i][k];
#pragma unroll
            for (int j = 0; j < 8; j++) rb[j] = sB[k][tx + 16 * j];
#pragma unroll
            for (int i = 0; i < 8; i++)
#pragma unroll
                for (int j = 0; j < 8; j++)
                    acc[i][j] = fmaf(ra[i], rb[j], acc[i][j]);
        }
        __syncthreads();
    }

#pragma unroll
    for (int i = 0; i < 8; i++) {
        int m = rowbase + ty + 16 * i;
#pragma unroll
        for (int j = 0; j < 8; j++) {
            int c = tx + 16 * j;
            if (c < 64) g_Q[(size_t)m * DKK + c] = acc[i][j];
            else        g_K[(size_t)m * DKK + (c - 64)] = acc[i][j];
        }
    }
}

// ---------------------------------------------------------------------------
// Kernel 2: score tile 128x128 via tensor cores (mma.sync m16n8k8 tf32).
// Inputs rounded to tf32 (rna) at smem-store time; accumulate fp32.
// Fused epilogue: u = exp(10*tanh(x))*e^-10 = exp(-20/(e^{2x}+1)),
// diagonal forced to 0, per-batch Z accumulated via warp-reduce + atomics.
// 8 warps; warp tile 32x64 (2 m16-tiles x 8 n8-tiles).
// ---------------------------------------------------------------------------
__device__ __forceinline__ float uval(float x, int qg, int sg) {
    float e2 = __expf(2.f * x);
    float u  = __expf(-__fdividef(20.f, e2 + 1.f));
    return (qg == sg) ? 0.f : u;
}

__global__ __launch_bounds__(256) void score_kernel(float* __restrict__ out)
{
    __shared__ uint32_t sQ[128][36];   // 32 k-cols staged, stride 36: banks 4m+k -> conflict-free
    __shared__ uint32_t sK[128][36];

    const int tid  = threadIdx.x;
    const int lane = tid & 31, warp = tid >> 5;
    const int bz    = blockIdx.z;
    const int qbase = blockIdx.y * 128;
    const int sbase = blockIdx.x * 128;

    const float* Qb = g_Q + (size_t)bz * SS * DKK;
    const float* Kb = g_K + (size_t)bz * SS * DKK;

    const int mrow = (warp & 3) * 32;   // warp row offset in tile
    const int ncol = (warp >> 2) * 64;  // warp col offset in tile
    const int g  = lane >> 2;           // 0..7
    const int tr = lane & 3;            // 0..3

    float acc[2][8][4];
#pragma unroll
    for (int mt = 0; mt < 2; mt++)
#pragma unroll
        for (int nt = 0; nt < 8; nt++)
#pragma unroll
            for (int r = 0; r < 4; r++) acc[mt][nt][r] = 0.f;

    for (int ks = 0; ks < DKK; ks += 32) {
        // stage 128 rows x 32 k of Q and K, converting to tf32 (rna)
#pragma unroll
        for (int it = 0; it < 4; it++) {
            int f = tid + 256 * it;
            int m = f >> 3, k4 = (f & 7) * 4;
            float4 q = *(const float4*)(Qb + (size_t)(qbase + m) * DKK + ks + k4);
            float4 k = *(const float4*)(Kb + (size_t)(sbase + m) * DKK + ks + k4);
            sQ[m][k4 + 0] = f2tf32(q.x); sQ[m][k4 + 1] = f2tf32(q.y);
            sQ[m][k4 + 2] = f2tf32(q.z); sQ[m][k4 + 3] = f2tf32(q.w);
            sK[m][k4 + 0] = f2tf32(k.x); sK[m][k4 + 1] = f2tf32(k.y);
            sK[m][k4 + 2] = f2tf32(k.z); sK[m][k4 + 3] = f2tf32(k.w);
        }
        __syncthreads();

#pragma unroll
        for (int kc = 0; kc < 4; kc++) {
            const int k0 = kc * 8;
            uint32_t a[2][4];
#pragma unroll
            for (int mt = 0; mt < 2; mt++) {
                int r = mrow + mt * 16 + g;
                a[mt][0] = sQ[r][k0 + tr];
                a[mt][1] = sQ[r + 8][k0 + tr];
                a[mt][2] = sQ[r][k0 + tr + 4];
                a[mt][3] = sQ[r + 8][k0 + tr + 4];
            }
#pragma unroll
            for (int nt = 0; nt < 8; nt++) {
                int c = ncol + nt * 8 + g;
                uint32_t b0 = sK[c][k0 + tr];
                uint32_t b1 = sK[c][k0 + tr + 4];
#pragma unroll
                for (int mt = 0; mt < 2; mt++) {
                    asm volatile(
                        "mma.sync.aligned.m16n8k8.row.col.f32.tf32.tf32.f32 "
                        "{%0,%1,%2,%3}, {%4,%5,%6,%7}, {%8,%9}, {%0,%1,%2,%3};"
                        : "+f"(acc[mt][nt][0]), "+f"(acc[mt][nt][1]),
                          "+f"(acc[mt][nt][2]), "+f"(acc[mt][nt][3])
                        : "r"(a[mt][0]), "r"(a[mt][1]), "r"(a[mt][2]), "r"(a[mt][3]),
                          "r"(b0), "r"(b1));
                }
            }
        }
        __syncthreads();
    }

    // fused epilogue: tanh->exp transform, diag mask, store, Z partial sum
    float local = 0.f;
    float* orow = out + ((size_t)bz << 20);
#pragma unroll
    for (int mt = 0; mt < 2; mt++) {
        int r0 = qbase + mrow + mt * 16 + g;
#pragma unroll
        for (int nt = 0; nt < 8; nt++) {
            int c = sbase + ncol + nt * 8 + tr * 2;
            float u0 = uval(acc[mt][nt][0], r0,     c);
            float u1 = uval(acc[mt][nt][1], r0,     c + 1);
            float u2 = uval(acc[mt][nt][2], r0 + 8, c);
            float u3 = uval(acc[mt][nt][3], r0 + 8, c + 1);
            *(float2*)(orow + (size_t)r0 * SS + c)       = make_float2(u0, u1);
            *(float2*)(orow + (size_t)(r0 + 8) * SS + c) = make_float2(u2, u3);
            local += (u0 + u1) + (u2 + u3);
        }
    }
#pragma unroll
    for (int o = 16; o; o >>= 1)
        local += __shfl_down_sync(0xffffffffu, local, o);
    if (lane == 0) atomicAdd(&g_Z[bz], local);
}

// ---------------------------------------------------------------------------
// Kernel 3: normalize by 1/Z[b]. float4 vectorized.
// ---------------------------------------------------------------------------
__global__ __launch_bounds__(256) void norm_kernel(float4* __restrict__ out)
{
    __shared__ float sinv;
    const int b = blockIdx.y;
    if (threadIdx.x == 0) sinv = 1.0f / g_Z[b];
    __syncthreads();
    const float inv = sinv;

    size_t idx = ((size_t)b << 18) + (size_t)blockIdx.x * 256 + threadIdx.x;
    float4 v = out[idx];
    v.x *= inv; v.y *= inv; v.z *= inv; v.w *= inv;
    out[idx] = v;
}

// ---------------------------------------------------------------------------
extern "C" void kernel_launch(void* const* d_in, const int* in_sizes, int n_in,
                              void* d_out, int out_size)
{
    const float* q  = (const float*)d_in[0];   // query [48,1024,128]
    const float* wq = (const float*)d_in[3];   // W_query [128,64]
    const float* wk = (const float*)d_in[4];   // W_key   [128,64]
    float* out = (float*)d_out;                // [48, 1024*1024] fp32

    proj_kernel<<<384, 256>>>(q, wq, wk);
    score_kernel<<<dim3(8, 8, NB), 256>>>(out);
    norm_kernel<<<dim3(1024, NB), 256>>>((float4*)out);
}

// round 3
// speedup vs baseline: 1.6248x; 1.1135x over previous
#include <cuda_runtime.h>
#include <math.h>
#include <stdint.h>

#define NB 48
#define SS 1024
#define DD 128
#define DKK 64

// scratch (static device globals: allocation-free per harness rules)
__device__ float g_Q[NB * SS * DKK];
__device__ float g_K[NB * SS * DKK];
__device__ float g_Z[NB];
// W split into tf32 hi/lo, TRANSPOSED to [n][k] (n: 0..63 Wq, 64..127 Wk)
__device__ uint32_t g_WhT[DD * DD];
__device__ uint32_t g_WlT[DD * DD];

__device__ __forceinline__ uint32_t f2tf32(float v) {
    uint32_t r;
    asm("cvt.rna.tf32.f32 %0, %1;" : "=r"(r) : "f"(v));
    return r;
}

// ---------------------------------------------------------------------------
// Kernel 0: split W into tf32 hi/lo and transpose to [n][k]; zero g_Z.
// 16384 elements, trivial cost.
// ---------------------------------------------------------------------------
__global__ __launch_bounds__(256) void setup_kernel(
    const float* __restrict__ Wq, const float* __restrict__ Wk)
{
    int idx = blockIdx.x * 256 + threadIdx.x;   // grid 64 -> 16384
    int k = idx >> 7, n = idx & 127;
    float v = (n < 64) ? Wq[k * DKK + n] : Wk[k * DKK + (n - 64)];
    uint32_t hi = f2tf32(v);
    uint32_t lo = f2tf32(v - __uint_as_float(hi));
    g_WhT[n * DD + k] = hi;
    g_WlT[n * DD + k] = lo;
    if (idx < NB) g_Z[idx] = 0.f;
}

// ---------------------------------------------------------------------------
// Kernel 1: fused Q|K projection on tensor cores, 3xTF32 split precision.
// C[49152,128] = A[49152,128] @ W[128,128]  (cols 0..63 -> g_Q, 64..127 -> g_K)
// A split to hi/lo at smem-staging time; W pre-split/transposed by setup.
// C ~= Ah*Wh + Ah*Wl + Al*Wh  (Al*Wl ~ 1e-7 rel, dropped) => fp32-like accuracy.
// CTA tile 128x128, K staged in 4 chunks of 32, 8 warps, warp tile 32x64.
// Dynamic smem: 4 arrays [128][36] u32 = 73728 B.
// ---------------------------------------------------------------------------
#define PROJ_SMEM (4 * 128 * 36 * 4)

__global__ __launch_bounds__(256) void proj_kernel(const float* __restrict__ A)
{
    extern __shared__ uint32_t smem[];
    uint32_t* sAh = smem;                 // [128][36]
    uint32_t* sAl = sAh + 128 * 36;
    uint32_t* sWh = sAl + 128 * 36;       // [n][k] transposed
    uint32_t* sWl = sWh + 128 * 36;

    const int tid  = threadIdx.x;
    const int lane = tid & 31, warp = tid >> 5;
    const int rowbase = blockIdx.x * 128;

    const int mrow = (warp & 3) * 32;
    const int ncol = (warp >> 2) * 64;
    const int g  = lane >> 2;
    const int tr = lane & 3;

    float acc[2][8][4];
#pragma unroll
    for (int mt = 0; mt < 2; mt++)
#pragma unroll
        for (int nt = 0; nt < 8; nt++)
#pragma unroll
            for (int r = 0; r < 4; r++) acc[mt][nt][r] = 0.f;

    for (int k0 = 0; k0 < DD; k0 += 32) {
        // stage A chunk 128x32 with tf32 hi/lo split
#pragma unroll
        for (int it = 0; it < 4; it++) {
            int f = tid + 256 * it;
            int m = f >> 3, k4 = (f & 7) * 4;
            float4 v = *(const float4*)(A + (size_t)(rowbase + m) * DD + k0 + k4);
            uint32_t h0 = f2tf32(v.x), h1 = f2tf32(v.y),
                     h2 = f2tf32(v.z), h3 = f2tf32(v.w);
            sAh[m * 36 + k4 + 0] = h0; sAh[m * 36 + k4 + 1] = h1;
            sAh[m * 36 + k4 + 2] = h2; sAh[m * 36 + k4 + 3] = h3;
            sAl[m * 36 + k4 + 0] = f2tf32(v.x - __uint_as_float(h0));
            sAl[m * 36 + k4 + 1] = f2tf32(v.y - __uint_as_float(h1));
            sAl[m * 36 + k4 + 2] = f2tf32(v.z - __uint_as_float(h2));
            sAl[m * 36 + k4 + 3] = f2tf32(v.w - __uint_as_float(h3));
        }
        // stage W chunk [n][32] (already split/transposed in global)
#pragma unroll
        for (int it = 0; it < 4; it++) {
            int f = tid + 256 * it;
            int n = f >> 3, k4 = (f & 7) * 4;
            uint4 h = *(const uint4*)(g_WhT + n * DD + k0 + k4);
            uint4 l = *(const uint4*)(g_WlT + n * DD + k0 + k4);
            sWh[n * 36 + k4 + 0] = h.x; sWh[n * 36 + k4 + 1] = h.y;
            sWh[n * 36 + k4 + 2] = h.z; sWh[n * 36 + k4 + 3] = h.w;
            sWl[n * 36 + k4 + 0] = l.x; sWl[n * 36 + k4 + 1] = l.y;
            sWl[n * 36 + k4 + 2] = l.z; sWl[n * 36 + k4 + 3] = l.w;
        }
        __syncthreads();

#pragma unroll
        for (int kc = 0; kc < 4; kc++) {
            const int kk = kc * 8;
            uint32_t ah[2][4], al[2][4];
#pragma unroll
            for (int mt = 0; mt < 2; mt++) {
                int r = mrow + mt * 16 + g;
                ah[mt][0] = sAh[r * 36 + kk + tr];
                ah[mt][1] = sAh[(r + 8) * 36 + kk + tr];
                ah[mt][2] = sAh[r * 36 + kk + tr + 4];
                ah[mt][3] = sAh[(r + 8) * 36 + kk + tr + 4];
                al[mt][0] = sAl[r * 36 + kk + tr];
                al[mt][1] = sAl[(r + 8) * 36 + kk + tr];
                al[mt][2] = sAl[r * 36 + kk + tr + 4];
                al[mt][3] = sAl[(r + 8) * 36 + kk + tr + 4];
            }
#pragma unroll
            for (int nt = 0; nt < 8; nt++) {
                int c = ncol + nt * 8 + g;
                uint32_t bh0 = sWh[c * 36 + kk + tr];
                uint32_t bh1 = sWh[c * 36 + kk + tr + 4];
                uint32_t bl0 = sWl[c * 36 + kk + tr];
                uint32_t bl1 = sWl[c * 36 + kk + tr + 4];
#pragma unroll
                for (int mt = 0; mt < 2; mt++) {
                    asm volatile(
                        "mma.sync.aligned.m16n8k8.row.col.f32.tf32.tf32.f32 "
                        "{%0,%1,%2,%3}, {%4,%5,%6,%7}, {%8,%9}, {%0,%1,%2,%3};"
                        : "+f"(acc[mt][nt][0]), "+f"(acc[mt][nt][1]),
                          "+f"(acc[mt][nt][2]), "+f"(acc[mt][nt][3])
                        : "r"(ah[mt][0]), "r"(ah[mt][1]), "r"(ah[mt][2]), "r"(ah[mt][3]),
                          "r"(bh0), "r"(bh1));
                    asm volatile(
                        "mma.sync.aligned.m16n8k8.row.col.f32.tf32.tf32.f32 "
                        "{%0,%1,%2,%3}, {%4,%5,%6,%7}, {%8,%9}, {%0,%1,%2,%3};"
                        : "+f"(acc[mt][nt][0]), "+f"(acc[mt][nt][1]),
                          "+f"(acc[mt][nt][2]), "+f"(acc[mt][nt][3])
                        : "r"(ah[mt][0]), "r"(ah[mt][1]), "r"(ah[mt][2]), "r"(ah[mt][3]),
                          "r"(bl0), "r"(bl1));
                    asm volatile(
                        "mma.sync.aligned.m16n8k8.row.col.f32.tf32.tf32.f32 "
                        "{%0,%1,%2,%3}, {%4,%5,%6,%7}, {%8,%9}, {%0,%1,%2,%3};"
                        : "+f"(acc[mt][nt][0]), "+f"(acc[mt][nt][1]),
                          "+f"(acc[mt][nt][2]), "+f"(acc[mt][nt][3])
                        : "r"(al[mt][0]), "r"(al[mt][1]), "r"(al[mt][2]), "r"(al[mt][3]),
                          "r"(bh0), "r"(bh1));
                }
            }
        }
        __syncthreads();
    }

    // store: cols 0..63 -> g_Q, 64..127 -> g_K (ncol decides the whole warp)
#pragma unroll
    for (int mt = 0; mt < 2; mt++) {
        int m0 = rowbase + mrow + mt * 16 + g;
#pragma unroll
        for (int nt = 0; nt < 8; nt++) {
            int c = ncol + nt * 8 + tr * 2;
            float* dst = (c < 64) ? g_Q : g_K;
            int cc = c & 63;
            *(float2*)(dst + (size_t)m0 * DKK + cc) =
                make_float2(acc[mt][nt][0], acc[mt][nt][1]);
            *(float2*)(dst + (size_t)(m0 + 8) * DKK + cc) =
                make_float2(acc[mt][nt][2], acc[mt][nt][3]);
        }
    }
}

// ---------------------------------------------------------------------------
// Kernel 2: score tile 128x128 via mma.sync tf32 (validated R2, unchanged).
// u = exp(10*tanh(x))*e^-10 = exp(-20/(e^{2x}+1)); diag -> 0; Z via atomics.
// ---------------------------------------------------------------------------
__device__ __forceinline__ float uval(float x, int qg, int sg) {
    float e2 = __expf(2.f * x);
    float u  = __expf(-__fdividef(20.f, e2 + 1.f));
    return (qg == sg) ? 0.f : u;
}

__global__ __launch_bounds__(256) void score_kernel(float* __restrict__ out)
{
    __shared__ uint32_t sQ[128][36];
    __shared__ uint32_t sK[128][36];

    const int tid  = threadIdx.x;
    const int lane = tid & 31, warp = tid >> 5;
    const int bz    = blockIdx.z;
    const int qbase = blockIdx.y * 128;
    const int sbase = blockIdx.x * 128;

    const float* Qb = g_Q + (size_t)bz * SS * DKK;
    const float* Kb = g_K + (size_t)bz * SS * DKK;

    const int mrow = (warp & 3) * 32;
    const int ncol = (warp >> 2) * 64;
    const int g  = lane >> 2;
    const int tr = lane & 3;

    float acc[2][8][4];
#pragma unroll
    for (int mt = 0; mt < 2; mt++)
#pragma unroll
        for (int nt = 0; nt < 8; nt++)
#pragma unroll
            for (int r = 0; r < 4; r++) acc[mt][nt][r] = 0.f;

    for (int ks = 0; ks < DKK; ks += 32) {
#pragma unroll
        for (int it = 0; it < 4; it++) {
            int f = tid + 256 * it;
            int m = f >> 3, k4 = (f & 7) * 4;
            float4 q = *(const float4*)(Qb + (size_t)(qbase + m) * DKK + ks + k4);
            float4 k = *(const float4*)(Kb + (size_t)(sbase + m) * DKK + ks + k4);
            sQ[m][k4 + 0] = f2tf32(q.x); sQ[m][k4 + 1] = f2tf32(q.y);
            sQ[m][k4 + 2] = f2tf32(q.z); sQ[m][k4 + 3] = f2tf32(q.w);
            sK[m][k4 + 0] = f2tf32(k.x); sK[m][k4 + 1] = f2tf32(k.y);
            sK[m][k4 + 2] = f2tf32(k.z); sK[m][k4 + 3] = f2tf32(k.w);
        }
        __syncthreads();

#pragma unroll
        for (int kc = 0; kc < 4; kc++) {
            const int k0 = kc * 8;
            uint32_t a[2][4];
#pragma unroll
            for (int mt = 0; mt < 2; mt++) {
                int r = mrow + mt * 16 + g;
                a[mt][0] = sQ[r][k0 + tr];
                a[mt][1] = sQ[r + 8][k0 + tr];
                a[mt][2] = sQ[r][k0 + tr + 4];
                a[mt][3] = sQ[r + 8][k0 + tr + 4];
            }
#pragma unroll
            for (int nt = 0; nt < 8; nt++) {
                int c = ncol + nt * 8 + g;
                uint32_t b0 = sK[c][k0 + tr];
                uint32_t b1 = sK[c][k0 + tr + 4];
#pragma unroll
                for (int mt = 0; mt < 2; mt++) {
                    asm volatile(
                        "mma.sync.aligned.m16n8k8.row.col.f32.tf32.tf32.f32 "
                        "{%0,%1,%2,%3}, {%4,%5,%6,%7}, {%8,%9}, {%0,%1,%2,%3};"
                        : "+f"(acc[mt][nt][0]), "+f"(acc[mt][nt][1]),
                          "+f"(acc[mt][nt][2]), "+f"(acc[mt][nt][3])
                        : "r"(a[mt][0]), "r"(a[mt][1]), "r"(a[mt][2]), "r"(a[mt][3]),
                          "r"(b0), "r"(b1));
                }
            }
        }
        __syncthreads();
    }

    float local = 0.f;
    float* orow = out + ((size_t)bz << 20);
#pragma unroll
    for (int mt = 0; mt < 2; mt++) {
        int r0 = qbase + mrow + mt * 16 + g;
#pragma unroll
        for (int nt = 0; nt < 8; nt++) {
            int c = sbase + ncol + nt * 8 + tr * 2;
            float u0 = uval(acc[mt][nt][0], r0,     c);
            float u1 = uval(acc[mt][nt][1], r0,     c + 1);
            float u2 = uval(acc[mt][nt][2], r0 + 8, c);
            float u3 = uval(acc[mt][nt][3], r0 + 8, c + 1);
            *(float2*)(orow + (size_t)r0 * SS + c)       = make_float2(u0, u1);
            *(float2*)(orow + (size_t)(r0 + 8) * SS + c) = make_float2(u2, u3);
            local += (u0 + u1) + (u2 + u3);
        }
    }
#pragma unroll
    for (int o = 16; o; o >>= 1)
        local += __shfl_down_sync(0xffffffffu, local, o);
    if (lane == 0) atomicAdd(&g_Z[bz], local);
}

// ---------------------------------------------------------------------------
// Kernel 3: normalize by 1/Z[b]. 2 independent float4 per thread (MLP=2).
// grid (512, 48) x 256 threads.
// ---------------------------------------------------------------------------
__global__ __launch_bounds__(256) void norm_kernel(float4* __restrict__ out)
{
    __shared__ float sinv;
    const int b = blockIdx.y;
    if (threadIdx.x == 0) sinv = 1.0f / g_Z[b];
    __syncthreads();
    const float inv = sinv;

    size_t base = ((size_t)b << 18) + (size_t)blockIdx.x * 512 + threadIdx.x;
    float4 v0 = out[base];
    float4 v1 = out[base + 256];
    v0.x *= inv; v0.y *= inv; v0.z *= inv; v0.w *= inv;
    v1.x *= inv; v1.y *= inv; v1.z *= inv; v1.w *= inv;
    out[base]       = v0;
    out[base + 256] = v1;
}

// ---------------------------------------------------------------------------
extern "C" void kernel_launch(void* const* d_in, const int* in_sizes, int n_in,
                              void* d_out, int out_size)
{
    const float* q  = (const float*)d_in[0];   // query [48,1024,128]
    const float* wq = (const float*)d_in[3];   // W_query [128,64]
    const float* wk = (const float*)d_in[4];   // W_key   [128,64]
    float* out = (float*)d_out;                // [48, 1024*1024] fp32

    cudaFuncSetAttribute(proj_kernel,
                         cudaFuncAttributeMaxDynamicSharedMemorySize, PROJ_SMEM);

    setup_kernel<<<64, 256>>>(wq, wk);
    proj_kernel<<<384, 256, PROJ_SMEM>>>(q);
    score_kernel<<<dim3(8, 8, NB), 256>>>(out);
    norm_kernel<<<dim3(512, NB), 256>>>((float4*)out);
}

// round 4
// speedup vs baseline: 2.0615x; 1.2687x over previous
#include <cuda_runtime.h>
#include <math.h>
#include <stdint.h>

#define NB 48
#define SS 1024
#define DD 128
#define DKK 64

// scratch (static device globals: allocation-free per harness rules)
__device__ float g_Q[NB * SS * DKK];
__device__ float g_K[NB * SS * DKK];
__device__ float g_Z[NB];
__device__ int   g_cnt[NB];
// W split into tf32 hi/lo, TRANSPOSED to [n][k] (n: 0..63 Wq, 64..127 Wk)
__device__ uint32_t g_WhT[DD * DD];
__device__ uint32_t g_WlT[DD * DD];

__device__ __forceinline__ uint32_t f2tf32(float v) {
    uint32_t r;
    asm("cvt.rna.tf32.f32 %0, %1;" : "=r"(r) : "f"(v));
    return r;
}

// ---------------------------------------------------------------------------
// Kernel 0: split W into tf32 hi/lo and transpose to [n][k]; zero g_Z/g_cnt.
// ---------------------------------------------------------------------------
__global__ __launch_bounds__(256) void setup_kernel(
    const float* __restrict__ Wq, const float* __restrict__ Wk)
{
    int idx = blockIdx.x * 256 + threadIdx.x;   // grid 64 -> 16384
    int k = idx >> 7, n = idx & 127;
    float v = (n < 64) ? Wq[k * DKK + n] : Wk[k * DKK + (n - 64)];
    uint32_t hi = f2tf32(v);
    uint32_t lo = f2tf32(v - __uint_as_float(hi));
    g_WhT[n * DD + k] = hi;
    g_WlT[n * DD + k] = lo;
    if (idx < NB) { g_Z[idx] = 0.f; g_cnt[idx] = 0; }
}

// ---------------------------------------------------------------------------
// Kernel 1: fused Q|K projection on tensor cores, 3xTF32 split precision.
// (validated R3, unchanged)
// ---------------------------------------------------------------------------
#define PROJ_SMEM (4 * 128 * 36 * 4)

__global__ __launch_bounds__(256) void proj_kernel(const float* __restrict__ A)
{
    extern __shared__ uint32_t smem[];
    uint32_t* sAh = smem;                 // [128][36]
    uint32_t* sAl = sAh + 128 * 36;
    uint32_t* sWh = sAl + 128 * 36;       // [n][k] transposed
    uint32_t* sWl = sWh + 128 * 36;

    const int tid  = threadIdx.x;
    const int lane = tid & 31, warp = tid >> 5;
    const int rowbase = blockIdx.x * 128;

    const int mrow = (warp & 3) * 32;
    const int ncol = (warp >> 2) * 64;
    const int g  = lane >> 2;
    const int tr = lane & 3;

    float acc[2][8][4];
#pragma unroll
    for (int mt = 0; mt < 2; mt++)
#pragma unroll
        for (int nt = 0; nt < 8; nt++)
#pragma unroll
            for (int r = 0; r < 4; r++) acc[mt][nt][r] = 0.f;

    for (int k0 = 0; k0 < DD; k0 += 32) {
#pragma unroll
        for (int it = 0; it < 4; it++) {
            int f = tid + 256 * it;
            int m = f >> 3, k4 = (f & 7) * 4;
            float4 v = *(const float4*)(A + (size_t)(rowbase + m) * DD + k0 + k4);
            uint32_t h0 = f2tf32(v.x), h1 = f2tf32(v.y),
                     h2 = f2tf32(v.z), h3 = f2tf32(v.w);
            sAh[m * 36 + k4 + 0] = h0; sAh[m * 36 + k4 + 1] = h1;
            sAh[m * 36 + k4 + 2] = h2; sAh[m * 36 + k4 + 3] = h3;
            sAl[m * 36 + k4 + 0] = f2tf32(v.x - __uint_as_float(h0));
            sAl[m * 36 + k4 + 1] = f2tf32(v.y - __uint_as_float(h1));
            sAl[m * 36 + k4 + 2] = f2tf32(v.z - __uint_as_float(h2));
            sAl[m * 36 + k4 + 3] = f2tf32(v.w - __uint_as_float(h3));
        }
#pragma unroll
        for (int it = 0; it < 4; it++) {
            int f = tid + 256 * it;
            int n = f >> 3, k4 = (f & 7) * 4;
            uint4 h = *(const uint4*)(g_WhT + n * DD + k0 + k4);
            uint4 l = *(const uint4*)(g_WlT + n * DD + k0 + k4);
            sWh[n * 36 + k4 + 0] = h.x; sWh[n * 36 + k4 + 1] = h.y;
            sWh[n * 36 + k4 + 2] = h.z; sWh[n * 36 + k4 + 3] = h.w;
            sWl[n * 36 + k4 + 0] = l.x; sWl[n * 36 + k4 + 1] = l.y;
            sWl[n * 36 + k4 + 2] = l.z; sWl[n * 36 + k4 + 3] = l.w;
        }
        __syncthreads();

#pragma unroll
        for (int kc = 0; kc < 4; kc++) {
            const int kk = kc * 8;
            uint32_t ah[2][4], al[2][4];
#pragma unroll
            for (int mt = 0; mt < 2; mt++) {
                int r = mrow + mt * 16 + g;
                ah[mt][0] = sAh[r * 36 + kk + tr];
                ah[mt][1] = sAh[(r + 8) * 36 + kk + tr];
                ah[mt][2] = sAh[r * 36 + kk + tr + 4];
                ah[mt][3] = sAh[(r + 8) * 36 + kk + tr + 4];
                al[mt][0] = sAl[r * 36 + kk + tr];
                al[mt][1] = sAl[(r + 8) * 36 + kk + tr];
                al[mt][2] = sAl[r * 36 + kk + tr + 4];
                al[mt][3] = sAl[(r + 8) * 36 + kk + tr + 4];
            }
#pragma unroll
            for (int nt = 0; nt < 8; nt++) {
                int c = ncol + nt * 8 + g;
                uint32_t bh0 = sWh[c * 36 + kk + tr];
                uint32_t bh1 = sWh[c * 36 + kk + tr + 4];
                uint32_t bl0 = sWl[c * 36 + kk + tr];
                uint32_t bl1 = sWl[c * 36 + kk + tr + 4];
#pragma unroll
                for (int mt = 0; mt < 2; mt++) {
                    asm volatile(
                        "mma.sync.aligned.m16n8k8.row.col.f32.tf32.tf32.f32 "
                        "{%0,%1,%2,%3}, {%4,%5,%6,%7}, {%8,%9}, {%0,%1,%2,%3};"
                        : "+f"(acc[mt][nt][0]), "+f"(acc[mt][nt][1]),
                          "+f"(acc[mt][nt][2]), "+f"(acc[mt][nt][3])
                        : "r"(ah[mt][0]), "r"(ah[mt][1]), "r"(ah[mt][2]), "r"(ah[mt][3]),
                          "r"(bh0), "r"(bh1));
                    asm volatile(
                        "mma.sync.aligned.m16n8k8.row.col.f32.tf32.tf32.f32 "
                        "{%0,%1,%2,%3}, {%4,%5,%6,%7}, {%8,%9}, {%0,%1,%2,%3};"
                        : "+f"(acc[mt][nt][0]), "+f"(acc[mt][nt][1]),
                          "+f"(acc[mt][nt][2]), "+f"(acc[mt][nt][3])
                        : "r"(ah[mt][0]), "r"(ah[mt][1]), "r"(ah[mt][2]), "r"(ah[mt][3]),
                          "r"(bl0), "r"(bl1));
                    asm volatile(
                        "mma.sync.aligned.m16n8k8.row.col.f32.tf32.tf32.f32 "
                        "{%0,%1,%2,%3}, {%4,%5,%6,%7}, {%8,%9}, {%0,%1,%2,%3};"
                        : "+f"(acc[mt][nt][0]), "+f"(acc[mt][nt][1]),
                          "+f"(acc[mt][nt][2]), "+f"(acc[mt][nt][3])
                        : "r"(al[mt][0]), "r"(al[mt][1]), "r"(al[mt][2]), "r"(al[mt][3]),
                          "r"(bh0), "r"(bh1));
                }
            }
        }
        __syncthreads();
    }

#pragma unroll
    for (int mt = 0; mt < 2; mt++) {
        int m0 = rowbase + mrow + mt * 16 + g;
#pragma unroll
        for (int nt = 0; nt < 8; nt++) {
            int c = ncol + nt * 8 + tr * 2;
            float* dst = (c < 64) ? g_Q : g_K;
            int cc = c & 63;
            *(float2*)(dst + (size_t)m0 * DKK + cc) =
                make_float2(acc[mt][nt][0], acc[mt][nt][1]);
            *(float2*)(dst + (size_t)(m0 + 8) * DKK + cc) =
                make_float2(acc[mt][nt][2], acc[mt][nt][3]);
        }
    }
}

// ---------------------------------------------------------------------------
// Kernel 2: score tile + SELF-NORMALIZING epilogue.
// Linear grid: bid = [0,3072), batch = bid>>6 (contiguous in launch order so
// the oldest incomplete batch is always fully resident -> forward progress).
// Per CTA: GEMM (mma.sync tf32) -> u = exp(-20/(e^{2x}+1)) held in regs ->
// one atomicAdd into g_Z[b] -> fence -> count. Thread 0 spins until all 64
// tiles of the batch arrived, then the CTA scales its in-register u by 1/Z
// and writes the final normalized output ONCE (no norm pass, no re-read).
// ---------------------------------------------------------------------------
__device__ __forceinline__ float uval(float x, int qg, int sg) {
    float e2 = __expf(2.f * x);
    float u  = __expf(-__fdividef(20.f, e2 + 1.f));
    return (qg == sg) ? 0.f : u;
}

__global__ __launch_bounds__(256) void score_kernel(float* __restrict__ out)
{
    __shared__ uint32_t sQ[128][36];
    __shared__ uint32_t sK[128][36];
    __shared__ float swarp[8];
    __shared__ float sinv;

    const int tid  = threadIdx.x;
    const int lane = tid & 31, warp = tid >> 5;
    const int bz    = blockIdx.x >> 6;
    const int tile  = blockIdx.x & 63;
    const int qbase = (tile >> 3) * 128;
    const int sbase = (tile & 7) * 128;

    const float* Qb = g_Q + (size_t)bz * SS * DKK;
    const float* Kb = g_K + (size_t)bz * SS * DKK;

    const int mrow = (warp & 3) * 32;
    const int ncol = (warp >> 2) * 64;
    const int g  = lane >> 2;
    const int tr = lane & 3;

    float acc[2][8][4];
#pragma unroll
    for (int mt = 0; mt < 2; mt++)
#pragma unroll
        for (int nt = 0; nt < 8; nt++)
#pragma unroll
            for (int r = 0; r < 4; r++) acc[mt][nt][r] = 0.f;

    for (int ks = 0; ks < DKK; ks += 32) {
#pragma unroll
        for (int it = 0; it < 4; it++) {
            int f = tid + 256 * it;
            int m = f >> 3, k4 = (f & 7) * 4;
            float4 q = *(const float4*)(Qb + (size_t)(qbase + m) * DKK + ks + k4);
            float4 k = *(const float4*)(Kb + (size_t)(sbase + m) * DKK + ks + k4);
            sQ[m][k4 + 0] = f2tf32(q.x); sQ[m][k4 + 1] = f2tf32(q.y);
            sQ[m][k4 + 2] = f2tf32(q.z); sQ[m][k4 + 3] = f2tf32(q.w);
            sK[m][k4 + 0] = f2tf32(k.x); sK[m][k4 + 1] = f2tf32(k.y);
            sK[m][k4 + 2] = f2tf32(k.z); sK[m][k4 + 3] = f2tf32(k.w);
        }
        __syncthreads();

#pragma unroll
        for (int kc = 0; kc < 4; kc++) {
            const int k0 = kc * 8;
            uint32_t a[2][4];
#pragma unroll
            for (int mt = 0; mt < 2; mt++) {
                int r = mrow + mt * 16 + g;
                a[mt][0] = sQ[r][k0 + tr];
                a[mt][1] = sQ[r + 8][k0 + tr];
                a[mt][2] = sQ[r][k0 + tr + 4];
                a[mt][3] = sQ[r + 8][k0 + tr + 4];
            }
#pragma unroll
            for (int nt = 0; nt < 8; nt++) {
                int c = ncol + nt * 8 + g;
                uint32_t b0 = sK[c][k0 + tr];
                uint32_t b1 = sK[c][k0 + tr + 4];
#pragma unroll
                for (int mt = 0; mt < 2; mt++) {
                    asm volatile(
                        "mma.sync.aligned.m16n8k8.row.col.f32.tf32.tf32.f32 "
                        "{%0,%1,%2,%3}, {%4,%5,%6,%7}, {%8,%9}, {%0,%1,%2,%3};"
                        : "+f"(acc[mt][nt][0]), "+f"(acc[mt][nt][1]),
                          "+f"(acc[mt][nt][2]), "+f"(acc[mt][nt][3])
                        : "r"(a[mt][0]), "r"(a[mt][1]), "r"(a[mt][2]), "r"(a[mt][3]),
                          "r"(b0), "r"(b1));
                }
            }
        }
        __syncthreads();
    }

    // transform in place (u stays in registers), accumulate local sum
    float local = 0.f;
#pragma unroll
    for (int mt = 0; mt < 2; mt++) {
        int r0 = qbase + mrow + mt * 16 + g;
#pragma unroll
        for (int nt = 0; nt < 8; nt++) {
            int c = sbase + ncol + nt * 8 + tr * 2;
            float u0 = uval(acc[mt][nt][0], r0,     c);
            float u1 = uval(acc[mt][nt][1], r0,     c + 1);
            float u2 = uval(acc[mt][nt][2], r0 + 8, c);
            float u3 = uval(acc[mt][nt][3], r0 + 8, c + 1);
            acc[mt][nt][0] = u0; acc[mt][nt][1] = u1;
            acc[mt][nt][2] = u2; acc[mt][nt][3] = u3;
            local += (u0 + u1) + (u2 + u3);
        }
    }
    // block reduce -> one atomicAdd + arrival count
#pragma unroll
    for (int o = 16; o; o >>= 1)
        local += __shfl_down_sync(0xffffffffu, local, o);
    if (lane == 0) swarp[warp] = local;
    __syncthreads();
    if (tid == 0) {
        float tot = swarp[0];
#pragma unroll
        for (int w = 1; w < 8; w++) tot += swarp[w];
        atomicAdd(&g_Z[bz], tot);
        __threadfence();                       // Z visible before count
        atomicAdd(&g_cnt[bz], 1);
        // spin until the whole batch has contributed
        volatile int* vc = g_cnt;
        while (vc[bz] < 64) { }
        volatile float* vz = g_Z;
        sinv = 1.0f / vz[bz];
    }
    __syncthreads();
    const float inv = sinv;

    // single normalized write
    float* orow = out + ((size_t)bz << 20);
#pragma unroll
    for (int mt = 0; mt < 2; mt++) {
        int r0 = qbase + mrow + mt * 16 + g;
#pragma unroll
        for (int nt = 0; nt < 8; nt++) {
            int c = sbase + ncol + nt * 8 + tr * 2;
            *(float2*)(orow + (size_t)r0 * SS + c) =
                make_float2(acc[mt][nt][0] * inv, acc[mt][nt][1] * inv);
            *(float2*)(orow + (size_t)(r0 + 8) * SS + c) =
                make_float2(acc[mt][nt][2] * inv, acc[mt][nt][3] * inv);
        }
    }
}

// ---------------------------------------------------------------------------
extern "C" void kernel_launch(void* const* d_in, const int* in_sizes, int n_in,
                              void* d_out, int out_size)
{
    const float* q  = (const float*)d_in[0];   // query [48,1024,128]
    const float* wq = (const float*)d_in[3];   // W_query [128,64]
    const float* wk = (const float*)d_in[4];   // W_key   [128,64]
    float* out = (float*)d_out;                // [48, 1024*1024] fp32

    cudaFuncSetAttribute(proj_kernel,
                         cudaFuncAttributeMaxDynamicSharedMemorySize, PROJ_SMEM);

    setup_kernel<<<64, 256>>>(wq, wk);
    proj_kernel<<<384, 256, PROJ_SMEM>>>(q);
    score_kernel<<<3072, 256>>>(out);
}